// round 5
// baseline (speedup 1.0000x reference)
#include <cuda_runtime.h>
#include <cuda_bf16.h>
#include <cstdint>

#define BB  2
#define NN  16384
#define MM  4096
#define C1_ 128
#define C2_ 256
#define H1_ 256
#define H2_ 128

// ---------------------------------------------------------------------------
// Scratch
// ---------------------------------------------------------------------------
__device__ int3   g_idx[BB * NN];
__device__ float3 g_wts[BB * NN];
__device__ float  g_Gt[(size_t)BB * MM * H1_];   // (B, M, H1) point-major
__device__ float  g_Ut[(size_t)BB * NN * H1_];   // (B, N, H1) point-major
__device__ float  g_h [(size_t)BB * H1_ * NN];   // (B, H1, N) channel-major

// ---------------------------------------------------------------------------
// f32x2 helpers
// ---------------------------------------------------------------------------
__device__ __forceinline__ uint32_t smem_u32(const void* p) {
    uint32_t a;
    asm("{ .reg .u64 t; cvta.to.shared.u64 t, %1; cvt.u32.u64 %0, t; }" : "=r"(a) : "l"(p));
    return a;
}
__device__ __forceinline__ void lds_v2u64(uint64_t& a, uint64_t& b, uint32_t addr) {
    asm volatile("ld.shared.v2.b64 {%0,%1}, [%2];" : "=l"(a), "=l"(b) : "r"(addr));
}
__device__ __forceinline__ void ffma2(uint64_t& d, uint64_t a, uint64_t b) {
    asm volatile("fma.rn.f32x2 %0, %1, %2, %0;" : "+l"(d) : "l"(a), "l"(b));
}
__device__ __forceinline__ float2 unpk(uint64_t v) {
    float2 r;
    asm("mov.b64 {%0,%1}, %2;" : "=f"(r.x), "=f"(r.y) : "l"(v));
    return r;
}

// ---------------------------------------------------------------------------
// kNN: 4 threads per query, FMA-only scoring (score = 0.5|b|^2 - a.b)
// ---------------------------------------------------------------------------
__device__ __forceinline__ void ins3(float d, int i,
                                     float& s0, float& s1, float& s2,
                                     int& i0, int& i1, int& i2) {
    if (d < s2) {
        if (d < s1) {
            s2 = s1; i2 = i1;
            if (d < s0) { s1 = s0; i1 = i0; s0 = d; i0 = i; }
            else        { s1 = d;  i1 = i; }
        } else { s2 = d; i2 = i; }
    }
}

__global__ void knn_kernel(const float* __restrict__ unknown,
                           const float* __restrict__ known,
                           int3* __restrict__ idx_out,
                           float3* __restrict__ wts_out)
{
    extern __shared__ float sm[];
    float* sx = sm;
    float* sy = sm + MM;
    float* sz = sm + 2 * MM;
    float* sh = sm + 3 * MM;

    const int b   = blockIdx.y;
    const int tid = threadIdx.x;

    const float* kb = known + (size_t)b * MM * 3;
    for (int i = tid; i < MM; i += blockDim.x) {
        float x = kb[i * 3 + 0], y = kb[i * 3 + 1], z = kb[i * 3 + 2];
        sx[i] = x; sy[i] = y; sz[i] = z;
        sh[i] = 0.5f * (x * x + y * y + z * z);
    }
    __syncthreads();

    const int q     = blockIdx.x * 64 + (tid >> 2);
    const int slice = tid & 3;

    const float3 a = ((const float3*)unknown)[(size_t)b * NN + q];
    const float nax = -a.x, nay = -a.y, naz = -a.z;

    float s0 = 1e30f, s1 = 1e30f, s2 = 1e30f;
    int i0 = 0, i1 = 0, i2 = 0;

    const float4* x4 = (const float4*)sx + slice * (MM / 16);
    const float4* y4 = (const float4*)sy + slice * (MM / 16);
    const float4* z4 = (const float4*)sz + slice * (MM / 16);
    const float4* h4 = (const float4*)sh + slice * (MM / 16);
    const int mbase = slice * (MM / 4);

    #pragma unroll 2
    for (int j = 0; j < MM / 16; j++) {
        float4 X = x4[j], Y = y4[j], Z = z4[j], H = h4[j];
        float t0 = fmaf(X.x, nax, fmaf(Y.x, nay, fmaf(Z.x, naz, H.x)));
        float t1 = fmaf(X.y, nax, fmaf(Y.y, nay, fmaf(Z.y, naz, H.y)));
        float t2 = fmaf(X.z, nax, fmaf(Y.z, nay, fmaf(Z.z, naz, H.z)));
        float t3 = fmaf(X.w, nax, fmaf(Y.w, nay, fmaf(Z.w, naz, H.w)));
        float m = fminf(fminf(t0, t1), fminf(t2, t3));
        if (m < s2) {
            int mb = mbase + j * 4;
            ins3(t0, mb + 0, s0, s1, s2, i0, i1, i2);
            ins3(t1, mb + 1, s0, s1, s2, i0, i1, i2);
            ins3(t2, mb + 2, s0, s1, s2, i0, i1, i2);
            ins3(t3, mb + 3, s0, s1, s2, i0, i1, i2);
        }
    }

    #pragma unroll
    for (int delta = 1; delta <= 2; delta <<= 1) {
        float a0 = __shfl_xor_sync(0xFFFFFFFF, s0, delta);
        float a1 = __shfl_xor_sync(0xFFFFFFFF, s1, delta);
        float a2 = __shfl_xor_sync(0xFFFFFFFF, s2, delta);
        int b0 = __shfl_xor_sync(0xFFFFFFFF, i0, delta);
        int b1 = __shfl_xor_sync(0xFFFFFFFF, i1, delta);
        int b2 = __shfl_xor_sync(0xFFFFFFFF, i2, delta);
        ins3(a0, b0, s0, s1, s2, i0, i1, i2);
        ins3(a1, b1, s0, s1, s2, i0, i1, i2);
        ins3(a2, b2, s0, s1, s2, i0, i1, i2);
    }

    if (slice == 0) {
        float dx, dy, dz;
        dx = sx[i0] - a.x; dy = sy[i0] - a.y; dz = sz[i0] - a.z;
        float d0 = dx * dx + dy * dy + dz * dz;
        dx = sx[i1] - a.x; dy = sy[i1] - a.y; dz = sz[i1] - a.z;
        float d1 = dx * dx + dy * dy + dz * dz;
        dx = sx[i2] - a.x; dy = sy[i2] - a.y; dz = sz[i2] - a.z;
        float d2 = dx * dx + dy * dy + dz * dz;

        float r0 = 1.0f / (sqrtf(d0) + 1e-8f);
        float r1 = 1.0f / (sqrtf(d1) + 1e-8f);
        float r2 = 1.0f / (sqrtf(d2) + 1e-8f);
        float rs = 1.0f / (r0 + r1 + r2);
        idx_out[(size_t)b * NN + q] = make_int3(i0, i1, i2);
        wts_out[(size_t)b * NN + q] = make_float3(r0 * rs, r1 * rs, r2 * rs);
    }
}

// ---------------------------------------------------------------------------
// f32x2 SGEMM: C = W(O,K; ldW) @ X(K,P)  [per batch z]
//   STORE_PO = true  -> C stored (P, O) point-major
//   STORE_PO = false -> C stored (O, P); RELU_BIAS adds bias + relu
// Tile 64x64x16, 256 threads. Each thread: 4 (o) x 4 (p) outputs kept as
// 4x2 f32x2 accumulators. W staged DUPLICATED in smem as (w,w) pairs so the
// broadcast operand is pair-ready; X pairs are natural.
// ---------------------------------------------------------------------------
template <bool STORE_PO, bool RELU_BIAS>
__global__ void __launch_bounds__(256)
sgemm2_kernel(const float* __restrict__ Wm, int ldW,
              const float* __restrict__ X, long strideX,
              float* __restrict__ C, long strideC,
              const float* __restrict__ bias,
              int O, int P, int K)
{
    constexpr int BO = 64, BP = 64, BK = 16;
    __shared__ float2 Wd[BK][BO];   // duplicated pairs: Wd[k][o] = (w, w)
    __shared__ float  Xs[BK][BP];

    const float* Xb = X + (long)blockIdx.z * strideX;
    float*       Cb = C + (long)blockIdx.z * strideC;

    const int o0 = blockIdx.y * BO;
    const int p0 = blockIdx.x * BP;
    const int t  = threadIdx.x;
    const int tx = t & 15;          // P direction
    const int ty = t >> 4;          // O direction

    const int wo = t & 63, wk = (t >> 6) * 4;   // W tile load mapping
    const int xk = t >> 4, xp = (t & 15) * 4;   // X tile load mapping

    const uint32_t aWd = smem_u32(&Wd[0][0]);
    const uint32_t aXs = smem_u32(&Xs[0][0]);

    uint64_t acc[4][2] = {};

    for (int k0 = 0; k0 < K; k0 += BK) {
        // Stage W (duplicated) — lanes have consecutive wo, so STS is coalesced.
        float4 wv = *(const float4*)&Wm[(long)(o0 + wo) * ldW + k0 + wk];
        Wd[wk + 0][wo] = make_float2(wv.x, wv.x);
        Wd[wk + 1][wo] = make_float2(wv.y, wv.y);
        Wd[wk + 2][wo] = make_float2(wv.z, wv.z);
        Wd[wk + 3][wo] = make_float2(wv.w, wv.w);
        // Stage X
        float4 xv = *(const float4*)&Xb[(long)(k0 + xk) * P + p0 + xp];
        *(float4*)&Xs[xk][xp] = xv;
        __syncthreads();

        #pragma unroll
        for (int k = 0; k < BK; k++) {
            uint64_t da0, da1, da2, da3, x01, x23;
            lds_v2u64(da0, da1, aWd + (uint32_t)(k * (BO * 8) + ty * 32));
            lds_v2u64(da2, da3, aWd + (uint32_t)(k * (BO * 8) + ty * 32 + 16));
            lds_v2u64(x01, x23, aXs + (uint32_t)(k * (BP * 4) + tx * 16));
            ffma2(acc[0][0], da0, x01); ffma2(acc[0][1], da0, x23);
            ffma2(acc[1][0], da1, x01); ffma2(acc[1][1], da1, x23);
            ffma2(acc[2][0], da2, x01); ffma2(acc[2][1], da2, x23);
            ffma2(acc[3][0], da3, x01); ffma2(acc[3][1], da3, x23);
        }
        __syncthreads();
    }

    const int ot = o0 + ty * 4;
    const int pt = p0 + tx * 4;

    // Unpack accumulators: f[i][j] = C[ot+i][pt+j]
    float f[4][4];
    #pragma unroll
    for (int i = 0; i < 4; i++) {
        float2 u0 = unpk(acc[i][0]);
        float2 u1 = unpk(acc[i][1]);
        f[i][0] = u0.x; f[i][1] = u0.y; f[i][2] = u1.x; f[i][3] = u1.y;
    }

    if (RELU_BIAS) {
        #pragma unroll
        for (int i = 0; i < 4; i++) {
            float bi = bias[ot + i];
            #pragma unroll
            for (int j = 0; j < 4; j++)
                f[i][j] = fmaxf(f[i][j] + bi, 0.0f);
        }
    }

    if (STORE_PO) {
        #pragma unroll
        for (int j = 0; j < 4; j++) {
            float4 v = make_float4(f[0][j], f[1][j], f[2][j], f[3][j]);
            *(float4*)&Cb[(long)(pt + j) * O + ot] = v;
        }
    } else {
        #pragma unroll
        for (int i = 0; i < 4; i++) {
            float4 v = make_float4(f[i][0], f[i][1], f[i][2], f[i][3]);
            *(float4*)&Cb[(long)(ot + i) * P + pt] = v;
        }
    }
}

// ---------------------------------------------------------------------------
// Combine: h[b,o,n] = relu( sum_j w_j * Gt[b,idx_j,o] + Ut[b,n,o] + b1[o] )
// ---------------------------------------------------------------------------
__global__ void combine_kernel(const float* __restrict__ Gt,
                               const float* __restrict__ Ut,
                               const int3* __restrict__ idx,
                               const float3* __restrict__ wts,
                               const float* __restrict__ b1,
                               float* __restrict__ h)
{
    __shared__ float smh[H1_][33];

    const int b    = blockIdx.y;
    const int n0   = blockIdx.x * 32;
    const int t    = threadIdx.x;
    const int warp = t >> 5;
    const int lane = t & 31;
    const int n    = n0 + warp;

    const int3   id = idx[(size_t)b * NN + n];
    const float3 ww = wts[(size_t)b * NN + n];

    const float* g0 = Gt + ((long)b * MM + id.x) * H1_;
    const float* g1 = Gt + ((long)b * MM + id.y) * H1_;
    const float* g2 = Gt + ((long)b * MM + id.z) * H1_;
    const float* ut = Ut + ((long)b * NN + n) * H1_;

    #pragma unroll
    for (int rep = 0; rep < 2; rep++) {
        int q = rep * 128 + lane * 4;
        float4 a  = *(const float4*)&g0[q];
        float4 bb = *(const float4*)&g1[q];
        float4 c  = *(const float4*)&g2[q];
        float4 u  = *(const float4*)&ut[q];
        float4 bv = *(const float4*)&b1[q];
        smh[q + 0][warp] = fmaxf(ww.x * a.x + ww.y * bb.x + ww.z * c.x + u.x + bv.x, 0.0f);
        smh[q + 1][warp] = fmaxf(ww.x * a.y + ww.y * bb.y + ww.z * c.y + u.y + bv.y, 0.0f);
        smh[q + 2][warp] = fmaxf(ww.x * a.z + ww.y * bb.z + ww.z * c.z + u.z + bv.z, 0.0f);
        smh[q + 3][warp] = fmaxf(ww.x * a.w + ww.y * bb.w + ww.z * c.w + u.w + bv.w, 0.0f);
    }
    __syncthreads();

    #pragma unroll
    for (int rep = 0; rep < 8; rep++) {
        int o = rep * 32 + warp;
        h[((long)b * H1_ + o) * NN + n0 + lane] = smh[o][lane];
    }
}

// ---------------------------------------------------------------------------
// Launch
// ---------------------------------------------------------------------------
extern "C" void kernel_launch(void* const* d_in, const int* in_sizes, int n_in,
                              void* d_out, int out_size)
{
    const float* unknown      = (const float*)d_in[0];
    const float* known        = (const float*)d_in[1];
    const float* unknow_feats = (const float*)d_in[2];
    const float* known_feats  = (const float*)d_in[3];
    const float* W1           = (const float*)d_in[4];
    const float* b1           = (const float*)d_in[5];
    const float* W2           = (const float*)d_in[6];
    const float* b2           = (const float*)d_in[7];
    float* out = (float*)d_out;

    void *pGt, *pUt, *pH, *pIdx, *pWts;
    cudaGetSymbolAddress(&pGt,  g_Gt);
    cudaGetSymbolAddress(&pUt,  g_Ut);
    cudaGetSymbolAddress(&pH,   g_h);
    cudaGetSymbolAddress(&pIdx, g_idx);
    cudaGetSymbolAddress(&pWts, g_wts);

    const int knn_smem = 4 * MM * 4;  // 64KB
    cudaFuncSetAttribute(knn_kernel, cudaFuncAttributeMaxDynamicSharedMemorySize, knn_smem);

    // 1) 3-NN + weights (4 threads per query)
    knn_kernel<<<dim3(NN / 64, BB), 256, knn_smem>>>(unknown, known, (int3*)pIdx, (float3*)pWts);

    // 2) Gt[b,m,o] = sum_c W1[o,c] * known_feats[b,c,m]  (c in [0,256))
    sgemm2_kernel<true, false><<<dim3(MM / 64, H1_ / 64, BB), 256>>>(
        W1, C1_ + C2_, known_feats, (long)C2_ * MM,
        (float*)pGt, (long)MM * H1_, nullptr, H1_, MM, C2_);

    // 3) Ut[b,n,o] = sum_c W1[o,256+c] * unknow_feats[b,c,n]
    sgemm2_kernel<true, false><<<dim3(NN / 64, H1_ / 64, BB), 256>>>(
        W1 + C2_, C1_ + C2_, unknow_feats, (long)C1_ * NN,
        (float*)pUt, (long)NN * H1_, nullptr, H1_, NN, C1_);

    // 4) h = relu(gathered-weighted Gt + Ut + b1), stored (B, H1, N)
    combine_kernel<<<dim3(NN / 32, BB), 1024>>>(
        (const float*)pGt, (const float*)pUt, (const int3*)pIdx,
        (const float3*)pWts, b1, (float*)pH);

    // 5) out = relu(W2 @ h + b2), stored (B, H2, N)
    sgemm2_kernel<false, true><<<dim3(NN / 64, H2_ / 64, BB), 256>>>(
        W2, H1_, (const float*)pH, (long)H1_ * NN,
        out, (long)H2_ * NN, b2, H2_, NN, H1_);
}

// round 6
// speedup vs baseline: 1.1272x; 1.1272x over previous
#include <cuda_runtime.h>
#include <cuda_bf16.h>
#include <cstdint>

#define BB  2
#define NN  16384
#define MM  4096
#define C1_ 128
#define C2_ 256
#define H1_ 256
#define H2_ 128

// ---------------------------------------------------------------------------
// Scratch
// ---------------------------------------------------------------------------
__device__ int3   g_idx[BB * NN];
__device__ float3 g_wts[BB * NN];
__device__ float  g_Gt[(size_t)BB * MM * H1_];   // (B, M, H1) point-major
__device__ float  g_Ut[(size_t)BB * NN * H1_];   // (B, N, H1) point-major
__device__ float  g_h [(size_t)BB * H1_ * NN];   // (B, H1, N) channel-major

// ---------------------------------------------------------------------------
// kNN: 4 threads per query, FMA-only scoring (score = 0.5|b|^2 - a.b)
// ---------------------------------------------------------------------------
__device__ __forceinline__ void ins3(float d, int i,
                                     float& s0, float& s1, float& s2,
                                     int& i0, int& i1, int& i2) {
    if (d < s2) {
        if (d < s1) {
            s2 = s1; i2 = i1;
            if (d < s0) { s1 = s0; i1 = i0; s0 = d; i0 = i; }
            else        { s1 = d;  i1 = i; }
        } else { s2 = d; i2 = i; }
    }
}

__global__ void knn_kernel(const float* __restrict__ unknown,
                           const float* __restrict__ known,
                           int3* __restrict__ idx_out,
                           float3* __restrict__ wts_out)
{
    extern __shared__ float sm[];
    float* sx = sm;
    float* sy = sm + MM;
    float* sz = sm + 2 * MM;
    float* sh = sm + 3 * MM;

    const int b   = blockIdx.y;
    const int tid = threadIdx.x;

    const float* kb = known + (size_t)b * MM * 3;
    for (int i = tid; i < MM; i += blockDim.x) {
        float x = kb[i * 3 + 0], y = kb[i * 3 + 1], z = kb[i * 3 + 2];
        sx[i] = x; sy[i] = y; sz[i] = z;
        sh[i] = 0.5f * (x * x + y * y + z * z);
    }
    __syncthreads();

    const int q     = blockIdx.x * 64 + (tid >> 2);
    const int slice = tid & 3;

    const float3 a = ((const float3*)unknown)[(size_t)b * NN + q];
    const float nax = -a.x, nay = -a.y, naz = -a.z;

    float s0 = 1e30f, s1 = 1e30f, s2 = 1e30f;
    int i0 = 0, i1 = 0, i2 = 0;

    const float4* x4 = (const float4*)sx + slice * (MM / 16);
    const float4* y4 = (const float4*)sy + slice * (MM / 16);
    const float4* z4 = (const float4*)sz + slice * (MM / 16);
    const float4* h4 = (const float4*)sh + slice * (MM / 16);
    const int mbase = slice * (MM / 4);

    #pragma unroll 2
    for (int j = 0; j < MM / 16; j++) {
        float4 X = x4[j], Y = y4[j], Z = z4[j], H = h4[j];
        float t0 = fmaf(X.x, nax, fmaf(Y.x, nay, fmaf(Z.x, naz, H.x)));
        float t1 = fmaf(X.y, nax, fmaf(Y.y, nay, fmaf(Z.y, naz, H.y)));
        float t2 = fmaf(X.z, nax, fmaf(Y.z, nay, fmaf(Z.z, naz, H.z)));
        float t3 = fmaf(X.w, nax, fmaf(Y.w, nay, fmaf(Z.w, naz, H.w)));
        float m = fminf(fminf(t0, t1), fminf(t2, t3));
        if (m < s2) {
            int mb = mbase + j * 4;
            ins3(t0, mb + 0, s0, s1, s2, i0, i1, i2);
            ins3(t1, mb + 1, s0, s1, s2, i0, i1, i2);
            ins3(t2, mb + 2, s0, s1, s2, i0, i1, i2);
            ins3(t3, mb + 3, s0, s1, s2, i0, i1, i2);
        }
    }

    #pragma unroll
    for (int delta = 1; delta <= 2; delta <<= 1) {
        float a0 = __shfl_xor_sync(0xFFFFFFFF, s0, delta);
        float a1 = __shfl_xor_sync(0xFFFFFFFF, s1, delta);
        float a2 = __shfl_xor_sync(0xFFFFFFFF, s2, delta);
        int b0 = __shfl_xor_sync(0xFFFFFFFF, i0, delta);
        int b1 = __shfl_xor_sync(0xFFFFFFFF, i1, delta);
        int b2 = __shfl_xor_sync(0xFFFFFFFF, i2, delta);
        ins3(a0, b0, s0, s1, s2, i0, i1, i2);
        ins3(a1, b1, s0, s1, s2, i0, i1, i2);
        ins3(a2, b2, s0, s1, s2, i0, i1, i2);
    }

    if (slice == 0) {
        float dx, dy, dz;
        dx = sx[i0] - a.x; dy = sy[i0] - a.y; dz = sz[i0] - a.z;
        float d0 = dx * dx + dy * dy + dz * dz;
        dx = sx[i1] - a.x; dy = sy[i1] - a.y; dz = sz[i1] - a.z;
        float d1 = dx * dx + dy * dy + dz * dz;
        dx = sx[i2] - a.x; dy = sy[i2] - a.y; dz = sz[i2] - a.z;
        float d2 = dx * dx + dy * dy + dz * dz;

        float r0 = 1.0f / (sqrtf(d0) + 1e-8f);
        float r1 = 1.0f / (sqrtf(d1) + 1e-8f);
        float r2 = 1.0f / (sqrtf(d2) + 1e-8f);
        float rs = 1.0f / (r0 + r1 + r2);
        idx_out[(size_t)b * NN + q] = make_int3(i0, i1, i2);
        wts_out[(size_t)b * NN + q] = make_float3(r0 * rs, r1 * rs, r2 * rs);
    }
}

// ---------------------------------------------------------------------------
// SGEMM 128x128x16, 256 threads, 8x8 per thread, double-buffered smem.
//   C = W(O,K; ldW) @ X(K,P)  [per batch z]
//   STORE_PO = true  -> C stored (P, O) point-major
//   STORE_PO = false -> C stored (O, P); RELU_BIAS adds bias + relu
// ---------------------------------------------------------------------------
template <bool STORE_PO, bool RELU_BIAS>
__global__ void __launch_bounds__(256, 2)
sgemm_kernel(const float* __restrict__ Wm, int ldW,
             const float* __restrict__ X, long strideX,
             float* __restrict__ C, long strideC,
             const float* __restrict__ bias,
             int O, int P, int K)
{
    constexpr int BO = 128, BP = 128, BK = 16;
    __shared__ float Ws[2][BK][BO];
    __shared__ float Xs[2][BK][BP];

    const float* Xb = X + (long)blockIdx.z * strideX;
    float*       Cb = C + (long)blockIdx.z * strideC;

    const int o0 = blockIdx.y * BO;
    const int p0 = blockIdx.x * BP;
    const int t  = threadIdx.x;
    const int tx = t & 15;          // P direction (8 wide)
    const int ty = t >> 4;          // O direction (8 wide)

    // staging maps
    const int wo = t & 127, wk = (t >> 7) * 8;   // W: row o, 8 k's (2 float4)
    const int xk = t >> 4,  xp = (t & 15) * 8;   // X: row k, 8 p's (2 float4)

    const float* wsrc = Wm + (long)(o0 + wo) * ldW + wk;
    const float* xsrc = Xb + (long)xk * P + p0 + xp;

    float acc[8][8] = {};

    // prologue: stage tile 0
    {
        float4 w0 = *(const float4*)&wsrc[0];
        float4 w1 = *(const float4*)&wsrc[4];
        Ws[0][wk + 0][wo] = w0.x; Ws[0][wk + 1][wo] = w0.y;
        Ws[0][wk + 2][wo] = w0.z; Ws[0][wk + 3][wo] = w0.w;
        Ws[0][wk + 4][wo] = w1.x; Ws[0][wk + 5][wo] = w1.y;
        Ws[0][wk + 6][wo] = w1.z; Ws[0][wk + 7][wo] = w1.w;
        float4 x0 = *(const float4*)&xsrc[0];
        float4 x1 = *(const float4*)&xsrc[4];
        *(float4*)&Xs[0][xk][xp]     = x0;
        *(float4*)&Xs[0][xk][xp + 4] = x1;
    }
    __syncthreads();

    int buf = 0;
    for (int k0 = 0; k0 < K; k0 += BK) {
        const bool has_next = (k0 + BK < K);
        float4 w0, w1, x0, x1;
        if (has_next) {
            w0 = *(const float4*)&wsrc[k0 + BK];
            w1 = *(const float4*)&wsrc[k0 + BK + 4];
            x0 = *(const float4*)&xsrc[(long)(k0 + BK) * P];
            x1 = *(const float4*)&xsrc[(long)(k0 + BK) * P + 4];
        }

        #pragma unroll
        for (int k = 0; k < BK; k++) {
            float a[8], bvals[8];
            *(float4*)&a[0] = *(const float4*)&Ws[buf][k][ty * 8];
            *(float4*)&a[4] = *(const float4*)&Ws[buf][k][ty * 8 + 4];
            *(float4*)&bvals[0] = *(const float4*)&Xs[buf][k][tx * 8];
            *(float4*)&bvals[4] = *(const float4*)&Xs[buf][k][tx * 8 + 4];
            #pragma unroll
            for (int i = 0; i < 8; i++)
                #pragma unroll
                for (int j = 0; j < 8; j++)
                    acc[i][j] = fmaf(a[i], bvals[j], acc[i][j]);
        }

        if (has_next) {
            int nb = buf ^ 1;
            Ws[nb][wk + 0][wo] = w0.x; Ws[nb][wk + 1][wo] = w0.y;
            Ws[nb][wk + 2][wo] = w0.z; Ws[nb][wk + 3][wo] = w0.w;
            Ws[nb][wk + 4][wo] = w1.x; Ws[nb][wk + 5][wo] = w1.y;
            Ws[nb][wk + 6][wo] = w1.z; Ws[nb][wk + 7][wo] = w1.w;
            *(float4*)&Xs[nb][xk][xp]     = x0;
            *(float4*)&Xs[nb][xk][xp + 4] = x1;
            __syncthreads();
            buf = nb;
        }
    }

    const int ot = o0 + ty * 8;
    const int pt = p0 + tx * 8;

    if (RELU_BIAS) {
        #pragma unroll
        for (int i = 0; i < 8; i++) {
            float bi = bias[ot + i];
            #pragma unroll
            for (int j = 0; j < 8; j++)
                acc[i][j] = fmaxf(acc[i][j] + bi, 0.0f);
        }
    }

    if (STORE_PO) {
        #pragma unroll
        for (int j = 0; j < 8; j++) {
            float4 v0 = make_float4(acc[0][j], acc[1][j], acc[2][j], acc[3][j]);
            float4 v1 = make_float4(acc[4][j], acc[5][j], acc[6][j], acc[7][j]);
            *(float4*)&Cb[(long)(pt + j) * O + ot]     = v0;
            *(float4*)&Cb[(long)(pt + j) * O + ot + 4] = v1;
        }
    } else {
        #pragma unroll
        for (int i = 0; i < 8; i++) {
            float4 v0 = make_float4(acc[i][0], acc[i][1], acc[i][2], acc[i][3]);
            float4 v1 = make_float4(acc[i][4], acc[i][5], acc[i][6], acc[i][7]);
            *(float4*)&Cb[(long)(ot + i) * P + pt]     = v0;
            *(float4*)&Cb[(long)(ot + i) * P + pt + 4] = v1;
        }
    }
}

// ---------------------------------------------------------------------------
// Combine: h[b,o,n] = relu( sum_j w_j * Gt[b,idx_j,o] + Ut[b,n,o] + b1[o] )
// ---------------------------------------------------------------------------
__global__ void combine_kernel(const float* __restrict__ Gt,
                               const float* __restrict__ Ut,
                               const int3* __restrict__ idx,
                               const float3* __restrict__ wts,
                               const float* __restrict__ b1,
                               float* __restrict__ h)
{
    __shared__ float smh[H1_][33];

    const int b    = blockIdx.y;
    const int n0   = blockIdx.x * 32;
    const int t    = threadIdx.x;
    const int warp = t >> 5;
    const int lane = t & 31;
    const int n    = n0 + warp;

    const int3   id = idx[(size_t)b * NN + n];
    const float3 ww = wts[(size_t)b * NN + n];

    const float* g0 = Gt + ((long)b * MM + id.x) * H1_;
    const float* g1 = Gt + ((long)b * MM + id.y) * H1_;
    const float* g2 = Gt + ((long)b * MM + id.z) * H1_;
    const float* ut = Ut + ((long)b * NN + n) * H1_;

    #pragma unroll
    for (int rep = 0; rep < 2; rep++) {
        int q = rep * 128 + lane * 4;
        float4 a  = *(const float4*)&g0[q];
        float4 bb = *(const float4*)&g1[q];
        float4 c  = *(const float4*)&g2[q];
        float4 u  = *(const float4*)&ut[q];
        float4 bv = *(const float4*)&b1[q];
        smh[q + 0][warp] = fmaxf(ww.x * a.x + ww.y * bb.x + ww.z * c.x + u.x + bv.x, 0.0f);
        smh[q + 1][warp] = fmaxf(ww.x * a.y + ww.y * bb.y + ww.z * c.y + u.y + bv.y, 0.0f);
        smh[q + 2][warp] = fmaxf(ww.x * a.z + ww.y * bb.z + ww.z * c.z + u.z + bv.z, 0.0f);
        smh[q + 3][warp] = fmaxf(ww.x * a.w + ww.y * bb.w + ww.z * c.w + u.w + bv.w, 0.0f);
    }
    __syncthreads();

    #pragma unroll
    for (int rep = 0; rep < 8; rep++) {
        int o = rep * 32 + warp;
        h[((long)b * H1_ + o) * NN + n0 + lane] = smh[o][lane];
    }
}

// ---------------------------------------------------------------------------
// Launch
// ---------------------------------------------------------------------------
extern "C" void kernel_launch(void* const* d_in, const int* in_sizes, int n_in,
                              void* d_out, int out_size)
{
    const float* unknown      = (const float*)d_in[0];
    const float* known        = (const float*)d_in[1];
    const float* unknow_feats = (const float*)d_in[2];
    const float* known_feats  = (const float*)d_in[3];
    const float* W1           = (const float*)d_in[4];
    const float* b1           = (const float*)d_in[5];
    const float* W2           = (const float*)d_in[6];
    const float* b2           = (const float*)d_in[7];
    float* out = (float*)d_out;

    void *pGt, *pUt, *pH, *pIdx, *pWts;
    cudaGetSymbolAddress(&pGt,  g_Gt);
    cudaGetSymbolAddress(&pUt,  g_Ut);
    cudaGetSymbolAddress(&pH,   g_h);
    cudaGetSymbolAddress(&pIdx, g_idx);
    cudaGetSymbolAddress(&pWts, g_wts);

    const int knn_smem = 4 * MM * 4;  // 64KB
    cudaFuncSetAttribute(knn_kernel, cudaFuncAttributeMaxDynamicSharedMemorySize, knn_smem);

    // 1) 3-NN + weights (4 threads per query)
    knn_kernel<<<dim3(NN / 64, BB), 256, knn_smem>>>(unknown, known, (int3*)pIdx, (float3*)pWts);

    // 2) Gt[b,m,o] = sum_c W1[o,c] * known_feats[b,c,m]  (c in [0,256))
    sgemm_kernel<true, false><<<dim3(MM / 128, H1_ / 128, BB), 256>>>(
        W1, C1_ + C2_, known_feats, (long)C2_ * MM,
        (float*)pGt, (long)MM * H1_, nullptr, H1_, MM, C2_);

    // 3) Ut[b,n,o] = sum_c W1[o,256+c] * unknow_feats[b,c,n]
    sgemm_kernel<true, false><<<dim3(NN / 128, H1_ / 128, BB), 256>>>(
        W1 + C2_, C1_ + C2_, unknow_feats, (long)C1_ * NN,
        (float*)pUt, (long)NN * H1_, nullptr, H1_, NN, C1_);

    // 4) h = relu(gathered-weighted Gt + Ut + b1), stored (B, H1, N)
    combine_kernel<<<dim3(NN / 32, BB), 1024>>>(
        (const float*)pGt, (const float*)pUt, (const int3*)pIdx,
        (const float3*)pWts, b1, (float*)pH);

    // 5) out = relu(W2 @ h + b2), stored (B, H2, N)
    sgemm_kernel<false, true><<<dim3(NN / 128, H2_ / 128, BB), 256>>>(
        W2, H1_, (const float*)pH, (long)H1_ * NN,
        out, (long)H2_ * NN, b2, H2_, NN, H1_);
}